// round 11
// baseline (speedup 1.0000x reference)
#include <cuda_runtime.h>

#define N_NODES 100000
#define N_EDGES 1600000
#define IN_CH   128
#define HID     32
#define HID2    64
#define OUT_CH  64
#define N_LAYERS 16

#define EPS_MSG 1e-7f
#define EPS_SM  1e-16f
#define EPS_BN  1e-5f

#define FULL 0xffffffffu
#define NBLK_F 12500      // fused kernel blocks: 8 warps/block, warp per node
#define SCAN_BLK 1024
#define SCAN_GRID ((N_NODES + SCAN_BLK - 1) / SCAN_BLK)   // 98
#define DBINS 256

// ---------------- scratch (static device globals; no allocation) -------------
__device__ float g_h [N_NODES * HID];     // current node features
__device__ float g_z [N_NODES * HID2];    // hidden MLP activations
__device__ int   g_deg[N_NODES];          // in-degree (prep)
__device__ int   g_off[N_NODES + 1];      // CSR offsets by dst
__device__ int   g_cur[N_NODES];          // fill cursors
__device__ int   g_srcs[N_EDGES];         // CSR: src*16 per edge, grouped by dst
__device__ int   g_bsum[SCAN_GRID];       // scan block sums
__device__ int   g_hist[DBINS];           // degree histogram
__device__ int   g_hcur[DBINS];           // degree-bin cursors
__device__ int   g_order[N_NODES];        // nodes grouped by degree
__device__ float g_psum[NBLK_F * HID2];   // BN partial sums
__device__ float g_psq [NBLK_F * HID2];   // BN partial sum-squares
__device__ float g_scale[HID2];
__device__ float g_shift[HID2];
__device__ int   g_is64;                  // 1 if edge_index is int64

// ---------------- detect edge_index dtype ------------------------------------
// int64 little-endian with values < 2^31 => every odd 32-bit word is 0.
__global__ void k_detect(const int* __restrict__ ei32) {
    __shared__ int any;
    if (threadIdx.x == 0) any = 0;
    __syncthreads();
    int v = ei32[2 * threadIdx.x + 1] | ei32[2 * (threadIdx.x + 1024) + 1];
    if (v != 0) any = 1;
    __syncthreads();
    if (threadIdx.x == 0) g_is64 = (any == 0) ? 1 : 0;
}

// ---------------- one-time CSR build -----------------------------------------
__global__ void k_zero_deg() {
    int i = blockIdx.x * 256 + threadIdx.x;
    if (i < N_NODES) g_deg[i] = 0;
    if (blockIdx.x == 0 && threadIdx.x < DBINS) g_hist[threadIdx.x] = 0;
}

__device__ __forceinline__ void raw_edge(const int* __restrict__ ei32,
                                         int e, int& s, int& d) {
    if (g_is64) { s = ei32[2 * e]; d = ei32[2 * (N_EDGES + e)]; }
    else        { s = ei32[e];     d = ei32[N_EDGES + e]; }
    s = min(max(s, 0), N_NODES - 1);
    d = min(max(d, 0), N_NODES - 1);
}

__global__ void k_deg(const int* __restrict__ ei32) {
    int e = blockIdx.x * 256 + threadIdx.x;
    if (e >= N_EDGES) return;
    int s, d; raw_edge(ei32, e, s, d);
    atomicAdd(&g_deg[d], 1);
}

// stage 1: per-block exclusive scan; local excl to g_off, block total to g_bsum
__global__ void k_scan1() {
    __shared__ int tmp[SCAN_BLK];
    int tid = threadIdx.x;
    int i = blockIdx.x * SCAN_BLK + tid;
    int v = (i < N_NODES) ? g_deg[i] : 0;
    tmp[tid] = v;
    __syncthreads();
    for (int o = 1; o < SCAN_BLK; o <<= 1) {
        int t = (tid >= o) ? tmp[tid - o] : 0;
        __syncthreads();
        tmp[tid] += t;
        __syncthreads();
    }
    if (i < N_NODES) g_off[i] = tmp[tid] - v;          // local exclusive
    if (tid == SCAN_BLK - 1) g_bsum[blockIdx.x] = tmp[tid];
}

// stage 2: one small block scans the 98 block sums (exclusive, in place)
__global__ void k_scan2() {
    __shared__ int tmp[128];
    int tid = threadIdx.x;
    int v = (tid < SCAN_GRID) ? g_bsum[tid] : 0;
    tmp[tid] = v;
    __syncthreads();
    for (int o = 1; o < 128; o <<= 1) {
        int t = (tid >= o) ? tmp[tid - o] : 0;
        __syncthreads();
        tmp[tid] += t;
        __syncthreads();
    }
    if (tid < SCAN_GRID) g_bsum[tid] = tmp[tid] - v;
    if (tid == 127) g_off[N_NODES] = tmp[tid];          // total = N_EDGES
}

// stage 3: add block offsets; init cursors; degree histogram
__global__ void k_scan3() {
    int i = blockIdx.x * SCAN_BLK + threadIdx.x;
    if (i >= N_NODES) return;
    int o = g_off[i] + g_bsum[blockIdx.x];
    g_off[i] = o;
    g_cur[i] = o;
    atomicAdd(&g_hist[min(g_deg[i], DBINS - 1)], 1);
}

__global__ void k_fill(const int* __restrict__ ei32) {
    int e = blockIdx.x * 256 + threadIdx.x;
    if (e >= N_EDGES) return;
    int s, d; raw_edge(ei32, e, s, d);
    int p = atomicAdd(&g_cur[d], 1);
    g_srcs[p] = s * 16;      // pre-scaled for float2 indexing
}

// degree-bin exclusive scan (1 block, 256 = DBINS)
__global__ void k_hscan() {
    __shared__ int tmp[DBINS];
    int tid = threadIdx.x;
    int v = g_hist[tid];
    tmp[tid] = v;
    __syncthreads();
    for (int o = 1; o < DBINS; o <<= 1) {
        int t = (tid >= o) ? tmp[tid - o] : 0;
        __syncthreads();
        tmp[tid] += t;
        __syncthreads();
    }
    g_hcur[tid] = tmp[tid] - v;
}

// scatter node ids grouped by degree -> warps in a block get equal-degree nodes
__global__ void k_scatter() {
    int i = blockIdx.x * 256 + threadIdx.x;
    if (i >= N_NODES) return;
    int bin = min(g_deg[i], DBINS - 1);
    int p = atomicAdd(&g_hcur[bin], 1);
    g_order[p] = i;
}

// ---------------- input projection: h = x @ w0 + b0 --------------------------
__global__ void k_input(const float* __restrict__ x,
                        const float* __restrict__ w0,
                        const float* __restrict__ b0) {
    __shared__ float sw[IN_CH * HID];
    __shared__ float sb[HID];
    int tid = threadIdx.x;
    for (int i = tid; i < IN_CH * HID; i += 256) sw[i] = w0[i];
    if (tid < HID) sb[tid] = b0[tid];
    __syncthreads();

    int n = blockIdx.x * 8 + (tid >> 5);
    int lane = tid & 31;
    if (n >= N_NODES) return;

    const float* xr = x + (long long)n * IN_CH;
    float acc = sb[lane];
#pragma unroll
    for (int k0 = 0; k0 < IN_CH; k0 += 32) {
        float xv = xr[k0 + lane];
#pragma unroll
        for (int j = 0; j < 32; j++) {
            float xb = __shfl_sync(FULL, xv, j);
            acc = fmaf(xb, sw[(k0 + j) * HID + lane], acc);
        }
    }
    g_h[n * HID + lane] = acc;
}

// ---------------- fused edge aggregation + MLP1 + BN partials ----------------
// Warp per dst node, nodes assigned in degree-grouped order (load balance:
// block time = max over its 8 warps; equal degrees -> max ~= mean).
// CSR gather from g_h: half-warp per edge, 2 channels per lane (float2),
// 4 independent gathers in flight; exp computed in-register.
// No max subtraction: m = relu(h)+eps is O(10) (BN renormalizes every layer),
// so exp(m) cannot overflow and num/den is shift-invariant.
__global__ void k_fused(const float* __restrict__ w1,
                        const float* __restrict__ b1) {
    __shared__ float sw[HID * HID2];
    __shared__ float sb[HID2];
    __shared__ float bsum[HID2], bsq[HID2];
    int tid = threadIdx.x;
    for (int i = tid; i < HID * HID2; i += 256) sw[i] = w1[i];
    if (tid < HID2) { sb[tid] = b1[tid]; bsum[tid] = 0.f; bsq[tid] = 0.f; }
    __syncthreads();

    int n = g_order[blockIdx.x * 8 + (tid >> 5)];   // grid*8 == N_NODES exactly
    int lane = tid & 31;

    int cp   = lane & 15;      // channel pair 0..15
    int half = lane >> 4;      // which edge of the pair
    int beg = g_off[n];
    int end = g_off[n + 1];
    const float2* __restrict__ h2 = (const float2*)g_h;

    float d0 = 0.f, m0s = 0.f, d1 = 0.f, m1s = 0.f;
    int i = beg + half;
    // 4-way unroll: four independent float2 gathers in flight per lane
    for (; i + 6 < end; i += 8) {
        float2 hA = h2[g_srcs[i]     + cp];
        float2 hB = h2[g_srcs[i + 2] + cp];
        float2 hC = h2[g_srcs[i + 4] + cp];
        float2 hD = h2[g_srcs[i + 6] + cp];
        float a0 = fmaxf(hA.x, 0.f) + EPS_MSG, a1 = fmaxf(hA.y, 0.f) + EPS_MSG;
        float b0v = fmaxf(hB.x, 0.f) + EPS_MSG, b1v = fmaxf(hB.y, 0.f) + EPS_MSG;
        float c0 = fmaxf(hC.x, 0.f) + EPS_MSG, c1 = fmaxf(hC.y, 0.f) + EPS_MSG;
        float e0v = fmaxf(hD.x, 0.f) + EPS_MSG, e1v = fmaxf(hD.y, 0.f) + EPS_MSG;
        float xA0 = __expf(a0), xA1 = __expf(a1);
        float xB0 = __expf(b0v), xB1 = __expf(b1v);
        float xC0 = __expf(c0), xC1 = __expf(c1);
        float xD0 = __expf(e0v), xD1 = __expf(e1v);
        d0  += (xA0 + xB0) + (xC0 + xD0);
        m0s += (xA0 * a0 + xB0 * b0v) + (xC0 * c0 + xD0 * e0v);
        d1  += (xA1 + xB1) + (xC1 + xD1);
        m1s += (xA1 * a1 + xB1 * b1v) + (xC1 * c1 + xD1 * e1v);
    }
    for (; i < end; i += 2) {
        float2 hA = h2[g_srcs[i] + cp];
        float a0 = fmaxf(hA.x, 0.f) + EPS_MSG, a1 = fmaxf(hA.y, 0.f) + EPS_MSG;
        float xA0 = __expf(a0), xA1 = __expf(a1);
        d0 += xA0;  m0s += xA0 * a0;
        d1 += xA1;  m1s += xA1 * a1;
    }
    // combine the two half-warps
    d0  += __shfl_xor_sync(FULL, d0, 16);
    m0s += __shfl_xor_sync(FULL, m0s, 16);
    d1  += __shfl_xor_sync(FULL, d1, 16);
    m1s += __shfl_xor_sync(FULL, m1s, 16);

    float2 hv = ((const float2*)g_h)[n * 16 + cp];
    float ov0 = m0s / (d0 + EPS_SM) + hv.x;   // channel 2*cp
    float ov1 = m1s / (d1 + EPS_SM) + hv.y;   // channel 2*cp+1

    // GEMM: z[n, :] = ov @ w1 + b1 ; lane c handles outputs c and c+32
    float a0 = sb[lane], a1 = sb[lane + 32];
#pragma unroll
    for (int q = 0; q < 16; q++) {
        float o0 = __shfl_sync(FULL, ov0, q);
        float o1 = __shfl_sync(FULL, ov1, q);
        a0 = fmaf(o0, sw[(2 * q) * HID2 + lane],          a0);
        a1 = fmaf(o0, sw[(2 * q) * HID2 + lane + 32],     a1);
        a0 = fmaf(o1, sw[(2 * q + 1) * HID2 + lane],      a0);
        a1 = fmaf(o1, sw[(2 * q + 1) * HID2 + lane + 32], a1);
    }
    g_z[n * HID2 + lane]      = a0;
    g_z[n * HID2 + lane + 32] = a1;

    atomicAdd(&bsum[lane],      a0); atomicAdd(&bsq[lane],      a0 * a0);
    atomicAdd(&bsum[lane + 32], a1); atomicAdd(&bsq[lane + 32], a1 * a1);
    __syncthreads();
    if (tid < HID2) {
        g_psum[blockIdx.x * HID2 + tid] = bsum[tid];
        g_psq [blockIdx.x * HID2 + tid] = bsq[tid];
    }
}

// ---------------- BN finalize: reduce partials; fold into scale/shift --------
__global__ void k_bn(const float* __restrict__ gamma,
                     const float* __restrict__ beta) {
    __shared__ float rs[256], rq[256];
    int c = blockIdx.x;
    int tid = threadIdx.x;
    float s = 0.f, q = 0.f;
    for (int b = tid; b < NBLK_F; b += 256) {
        s += g_psum[b * HID2 + c];
        q += g_psq [b * HID2 + c];
    }
    rs[tid] = s; rq[tid] = q;
    __syncthreads();
    for (int o = 128; o > 0; o >>= 1) {
        if (tid < o) { rs[tid] += rs[tid + o]; rq[tid] += rq[tid + o]; }
        __syncthreads();
    }
    if (tid == 0) {
        float mean = rs[0] / (float)N_NODES;
        float var  = rq[0] / (float)N_NODES - mean * mean;
        float rstd = rsqrtf(var + EPS_BN);
        float sc = gamma[c] * rstd;
        g_scale[c] = sc;
        g_shift[c] = beta[c] - mean * sc;
    }
}

// ---------------- node MLP part 2: h = relu(relu(BN(z)) @ w2 + b2) -----------
__global__ void k_mlp2(const float* __restrict__ w2,
                       const float* __restrict__ b2) {
    __shared__ float sw[HID2 * HID];
    __shared__ float sb[HID];
    __shared__ float ssc[HID2], ssh[HID2];
    int tid = threadIdx.x;
    for (int i = tid; i < HID2 * HID; i += 256) sw[i] = w2[i];
    if (tid < HID) sb[tid] = b2[tid];
    if (tid < HID2) { ssc[tid] = g_scale[tid]; ssh[tid] = g_shift[tid]; }
    __syncthreads();

    int n = blockIdx.x * 8 + (tid >> 5);
    int lane = tid & 31;
    if (n >= N_NODES) return;

    float y0 = fmaxf(fmaf(g_z[n * HID2 + lane],      ssc[lane],      ssh[lane]),      0.f);
    float y1 = fmaxf(fmaf(g_z[n * HID2 + lane + 32], ssc[lane + 32], ssh[lane + 32]), 0.f);
    float acc = sb[lane];
#pragma unroll
    for (int j = 0; j < 32; j++) {
        acc = fmaf(__shfl_sync(FULL, y0, j), sw[j * HID + lane],        acc);
        acc = fmaf(__shfl_sync(FULL, y1, j), sw[(j + 32) * HID + lane], acc);
    }
    g_h[n * HID + lane] = fmaxf(acc, 0.f);   // outer relu from the layer loop
}

// ---------------- output projection: out = h @ w16 + b16 ---------------------
__global__ void k_final(const float* __restrict__ w16,
                        const float* __restrict__ b16,
                        float* __restrict__ out) {
    __shared__ float sw[HID * OUT_CH];
    __shared__ float sb[OUT_CH];
    int tid = threadIdx.x;
    for (int i = tid; i < HID * OUT_CH; i += 256) sw[i] = w16[i];
    if (tid < OUT_CH) sb[tid] = b16[tid];
    __syncthreads();

    int n = blockIdx.x * 8 + (tid >> 5);
    int lane = tid & 31;
    if (n >= N_NODES) return;

    float hv = g_h[n * HID + lane];
    float a0 = sb[lane], a1 = sb[lane + 32];
#pragma unroll
    for (int j = 0; j < 32; j++) {
        float hb = __shfl_sync(FULL, hv, j);
        a0 = fmaf(hb, sw[j * OUT_CH + lane],      a0);
        a1 = fmaf(hb, sw[j * OUT_CH + lane + 32], a1);
    }
    out[n * OUT_CH + lane]      = a0;
    out[n * OUT_CH + lane + 32] = a1;
}

// -----------------------------------------------------------------------------
extern "C" void kernel_launch(void* const* d_in, const int* in_sizes, int n_in,
                              void* d_out, int out_size) {
    const float* x      = (const float*)d_in[0];
    const int*   ei32   = (const int*)d_in[1];     // int32 OR int64 (detected)
    const float* w0     = (const float*)d_in[2];
    const float* b0     = (const float*)d_in[3];
    const float* lin1_w = (const float*)d_in[4];
    const float* lin1_b = (const float*)d_in[5];
    const float* gamma  = (const float*)d_in[6];
    const float* beta   = (const float*)d_in[7];
    const float* lin2_w = (const float*)d_in[8];
    const float* lin2_b = (const float*)d_in[9];
    const float* w16    = (const float*)d_in[10];
    const float* b16    = (const float*)d_in[11];
    float* out = (float*)d_out;

    const int nodeBlocks = (N_NODES + 7) / 8;        // warp per node
    const int edgeBlocks = (N_EDGES + 255) / 256;
    const int nBlocks256 = (N_NODES + 255) / 256;

    // one-time per call: dtype detect + CSR build + degree-grouped node order
    k_detect<<<1, 1024>>>(ei32);
    k_zero_deg<<<nBlocks256, 256>>>();
    k_deg<<<edgeBlocks, 256>>>(ei32);
    k_scan1<<<SCAN_GRID, SCAN_BLK>>>();
    k_scan2<<<1, 128>>>();
    k_scan3<<<SCAN_GRID, SCAN_BLK>>>();
    k_fill<<<edgeBlocks, 256>>>(ei32);
    k_hscan<<<1, DBINS>>>();
    k_scatter<<<nBlocks256, 256>>>();

    k_input<<<nodeBlocks, 256>>>(x, w0, b0);
    for (int i = 0; i < N_LAYERS; i++) {
        k_fused<<<NBLK_F, 256>>>(lin1_w + i * HID * HID2, lin1_b + i * HID2);
        k_bn<<<HID2, 256>>>(gamma + i * HID2, beta + i * HID2);
        k_mlp2<<<nodeBlocks, 256>>>(lin2_w + i * HID2 * HID, lin2_b + i * HID);
    }
    k_final<<<nodeBlocks, 256>>>(w16, b16, out);
}

// round 12
// speedup vs baseline: 1.0189x; 1.0189x over previous
#include <cuda_runtime.h>

#define N_NODES 100000
#define N_EDGES 1600000
#define IN_CH   128
#define HID     32
#define HID2    64
#define OUT_CH  64
#define N_LAYERS 16

#define EPS_MSG 1e-7f
#define EPS_SM  1e-16f
#define EPS_BN  1e-5f

#define FULL 0xffffffffu
#define NBLK_F 12500      // fused kernel blocks: 8 warps/block, warp per node
#define SCAN_BLK 1024
#define SCAN_GRID ((N_NODES + SCAN_BLK - 1) / SCAN_BLK)   // 98

// ---------------- scratch (static device globals; no allocation) -------------
__device__ float g_h [N_NODES * HID];     // current node features
__device__ float g_z [N_NODES * HID2];    // hidden MLP activations
__device__ int   g_deg[N_NODES];          // in-degree (prep)
__device__ int   g_off[N_NODES + 1];      // CSR offsets by dst
__device__ int   g_cur[N_NODES];          // fill cursors
__device__ int   g_srcs[N_EDGES];         // CSR: src*8 per edge, grouped by dst
__device__ int   g_bsum[SCAN_GRID];       // scan block sums
__device__ float g_psum[NBLK_F * HID2];   // BN partial sums
__device__ float g_psq [NBLK_F * HID2];   // BN partial sum-squares
__device__ float g_scale[HID2];
__device__ float g_shift[HID2];
__device__ int   g_is64;                  // 1 if edge_index is int64

// ---------------- detect edge_index dtype ------------------------------------
// int64 little-endian with values < 2^31 => every odd 32-bit word is 0.
__global__ void k_detect(const int* __restrict__ ei32) {
    __shared__ int any;
    if (threadIdx.x == 0) any = 0;
    __syncthreads();
    int v = ei32[2 * threadIdx.x + 1] | ei32[2 * (threadIdx.x + 1024) + 1];
    if (v != 0) any = 1;
    __syncthreads();
    if (threadIdx.x == 0) g_is64 = (any == 0) ? 1 : 0;
}

// ---------------- one-time CSR build -----------------------------------------
__global__ void k_zero_deg() {
    int i = blockIdx.x * 256 + threadIdx.x;
    if (i < N_NODES) g_deg[i] = 0;
}

__device__ __forceinline__ void raw_edge(const int* __restrict__ ei32,
                                         int e, int& s, int& d) {
    if (g_is64) { s = ei32[2 * e]; d = ei32[2 * (N_EDGES + e)]; }
    else        { s = ei32[e];     d = ei32[N_EDGES + e]; }
    s = min(max(s, 0), N_NODES - 1);
    d = min(max(d, 0), N_NODES - 1);
}

__global__ void k_deg(const int* __restrict__ ei32) {
    int e = blockIdx.x * 256 + threadIdx.x;
    if (e >= N_EDGES) return;
    int s, d; raw_edge(ei32, e, s, d);
    atomicAdd(&g_deg[d], 1);
}

// stage 1: per-block exclusive scan; local excl to g_off, block total to g_bsum
__global__ void k_scan1() {
    __shared__ int tmp[SCAN_BLK];
    int tid = threadIdx.x;
    int i = blockIdx.x * SCAN_BLK + tid;
    int v = (i < N_NODES) ? g_deg[i] : 0;
    tmp[tid] = v;
    __syncthreads();
    for (int o = 1; o < SCAN_BLK; o <<= 1) {
        int t = (tid >= o) ? tmp[tid - o] : 0;
        __syncthreads();
        tmp[tid] += t;
        __syncthreads();
    }
    if (i < N_NODES) g_off[i] = tmp[tid] - v;          // local exclusive
    if (tid == SCAN_BLK - 1) g_bsum[blockIdx.x] = tmp[tid];
}

// stage 2: one small block scans the 98 block sums (exclusive, in place)
__global__ void k_scan2() {
    __shared__ int tmp[128];
    int tid = threadIdx.x;
    int v = (tid < SCAN_GRID) ? g_bsum[tid] : 0;
    tmp[tid] = v;
    __syncthreads();
    for (int o = 1; o < 128; o <<= 1) {
        int t = (tid >= o) ? tmp[tid - o] : 0;
        __syncthreads();
        tmp[tid] += t;
        __syncthreads();
    }
    if (tid < SCAN_GRID) g_bsum[tid] = tmp[tid] - v;
    if (tid == 127) g_off[N_NODES] = tmp[tid];          // total = N_EDGES
}

// stage 3: add block offsets; init cursors
__global__ void k_scan3() {
    int i = blockIdx.x * SCAN_BLK + threadIdx.x;
    if (i >= N_NODES) return;
    int o = g_off[i] + g_bsum[blockIdx.x];
    g_off[i] = o;
    g_cur[i] = o;
}

__global__ void k_fill(const int* __restrict__ ei32) {
    int e = blockIdx.x * 256 + threadIdx.x;
    if (e >= N_EDGES) return;
    int s, d; raw_edge(ei32, e, s, d);
    int p = atomicAdd(&g_cur[d], 1);
    g_srcs[p] = s * 8;       // pre-scaled for float4 indexing
}

// ---------------- input projection: h = x @ w0 + b0 --------------------------
__global__ void k_input(const float* __restrict__ x,
                        const float* __restrict__ w0,
                        const float* __restrict__ b0) {
    __shared__ float sw[IN_CH * HID];
    __shared__ float sb[HID];
    int tid = threadIdx.x;
    for (int i = tid; i < IN_CH * HID; i += 256) sw[i] = w0[i];
    if (tid < HID) sb[tid] = b0[tid];
    __syncthreads();

    int n = blockIdx.x * 8 + (tid >> 5);
    int lane = tid & 31;
    if (n >= N_NODES) return;

    const float* xr = x + (long long)n * IN_CH;
    float acc = sb[lane];
#pragma unroll
    for (int k0 = 0; k0 < IN_CH; k0 += 32) {
        float xv = xr[k0 + lane];
#pragma unroll
        for (int j = 0; j < 32; j++) {
            float xb = __shfl_sync(FULL, xv, j);
            acc = fmaf(xb, sw[(k0 + j) * HID + lane], acc);
        }
    }
    g_h[n * HID + lane] = acc;
}

// ---------------- fused edge aggregation + MLP1 + BN partials ----------------
// Warp per dst node (natural order: warps of a block stream contiguous CSR
// ranges — R11 showed this locality beats degree-balancing).
// Gather: quarter-warp per edge, 4 channels per lane via one float4 load;
// 2-deep unroll -> 8 edges in flight per warp. exp computed in-register.
// No max subtraction: m = relu(h)+eps is O(10) (BN renormalizes every layer),
// so exp(m) cannot overflow and num/den is shift-invariant.
__global__ void k_fused(const float* __restrict__ w1,
                        const float* __restrict__ b1) {
    __shared__ float sw[HID * HID2];
    __shared__ float sb[HID2];
    __shared__ float bsum[HID2], bsq[HID2];
    int tid = threadIdx.x;
    for (int i = tid; i < HID * HID2; i += 256) sw[i] = w1[i];
    if (tid < HID2) { sb[tid] = b1[tid]; bsum[tid] = 0.f; bsq[tid] = 0.f; }
    __syncthreads();

    int n = blockIdx.x * 8 + (tid >> 5);    // grid*8 == N_NODES exactly
    int lane = tid & 31;

    int c4      = lane & 7;    // float4 column (channels 4*c4 .. 4*c4+3)
    int quarter = lane >> 3;   // which edge of a group of 4
    int beg = g_off[n];
    int end = g_off[n + 1];
    const float4* __restrict__ h4 = (const float4*)g_h;

    float den[4] = {0.f, 0.f, 0.f, 0.f};
    float num[4] = {0.f, 0.f, 0.f, 0.f};
    int i = beg + quarter;
    // 2-deep unroll: two independent float4 gathers in flight per lane
    for (; i + 4 < end; i += 8) {
        float4 A = h4[g_srcs[i]     + c4];
        float4 B = h4[g_srcs[i + 4] + c4];
        float a0 = fmaxf(A.x, 0.f) + EPS_MSG, a1 = fmaxf(A.y, 0.f) + EPS_MSG;
        float a2 = fmaxf(A.z, 0.f) + EPS_MSG, a3 = fmaxf(A.w, 0.f) + EPS_MSG;
        float b0v = fmaxf(B.x, 0.f) + EPS_MSG, b1v = fmaxf(B.y, 0.f) + EPS_MSG;
        float b2v = fmaxf(B.z, 0.f) + EPS_MSG, b3v = fmaxf(B.w, 0.f) + EPS_MSG;
        float xa0 = __expf(a0), xa1 = __expf(a1), xa2 = __expf(a2), xa3 = __expf(a3);
        float xb0 = __expf(b0v), xb1 = __expf(b1v), xb2 = __expf(b2v), xb3 = __expf(b3v);
        den[0] += xa0 + xb0;  num[0] += xa0 * a0 + xb0 * b0v;
        den[1] += xa1 + xb1;  num[1] += xa1 * a1 + xb1 * b1v;
        den[2] += xa2 + xb2;  num[2] += xa2 * a2 + xb2 * b2v;
        den[3] += xa3 + xb3;  num[3] += xa3 * a3 + xb3 * b3v;
    }
    for (; i < end; i += 4) {
        float4 A = h4[g_srcs[i] + c4];
        float a0 = fmaxf(A.x, 0.f) + EPS_MSG, a1 = fmaxf(A.y, 0.f) + EPS_MSG;
        float a2 = fmaxf(A.z, 0.f) + EPS_MSG, a3 = fmaxf(A.w, 0.f) + EPS_MSG;
        float xa0 = __expf(a0), xa1 = __expf(a1), xa2 = __expf(a2), xa3 = __expf(a3);
        den[0] += xa0;  num[0] += xa0 * a0;
        den[1] += xa1;  num[1] += xa1 * a1;
        den[2] += xa2;  num[2] += xa2 * a2;
        den[3] += xa3;  num[3] += xa3 * a3;
    }
    // combine the four quarter-warps
#pragma unroll
    for (int c = 0; c < 4; c++) {
        den[c] += __shfl_xor_sync(FULL, den[c], 8);
        num[c] += __shfl_xor_sync(FULL, num[c], 8);
        den[c] += __shfl_xor_sync(FULL, den[c], 16);
        num[c] += __shfl_xor_sync(FULL, num[c], 16);
    }

    float4 hv = h4[n * 8 + c4];
    float ov[4];
    ov[0] = num[0] / (den[0] + EPS_SM) + hv.x;
    ov[1] = num[1] / (den[1] + EPS_SM) + hv.y;
    ov[2] = num[2] / (den[2] + EPS_SM) + hv.z;
    ov[3] = num[3] / (den[3] + EPS_SM) + hv.w;

    // GEMM: z[n, :] = ov @ w1 + b1 ; lane c handles outputs c and c+32
    float a0 = sb[lane], a1 = sb[lane + 32];
#pragma unroll
    for (int q = 0; q < 8; q++) {
#pragma unroll
        for (int c = 0; c < 4; c++) {
            float o = __shfl_sync(FULL, ov[c], q);
            int j = q * 4 + c;
            a0 = fmaf(o, sw[j * HID2 + lane],      a0);
            a1 = fmaf(o, sw[j * HID2 + lane + 32], a1);
        }
    }
    g_z[n * HID2 + lane]      = a0;
    g_z[n * HID2 + lane + 32] = a1;

    atomicAdd(&bsum[lane],      a0); atomicAdd(&bsq[lane],      a0 * a0);
    atomicAdd(&bsum[lane + 32], a1); atomicAdd(&bsq[lane + 32], a1 * a1);
    __syncthreads();
    if (tid < HID2) {
        g_psum[blockIdx.x * HID2 + tid] = bsum[tid];
        g_psq [blockIdx.x * HID2 + tid] = bsq[tid];
    }
}

// ---------------- BN finalize: reduce partials; fold into scale/shift --------
__global__ void k_bn(const float* __restrict__ gamma,
                     const float* __restrict__ beta) {
    __shared__ float rs[256], rq[256];
    int c = blockIdx.x;
    int tid = threadIdx.x;
    float s = 0.f, q = 0.f;
    for (int b = tid; b < NBLK_F; b += 256) {
        s += g_psum[b * HID2 + c];
        q += g_psq [b * HID2 + c];
    }
    rs[tid] = s; rq[tid] = q;
    __syncthreads();
    for (int o = 128; o > 0; o >>= 1) {
        if (tid < o) { rs[tid] += rs[tid + o]; rq[tid] += rq[tid + o]; }
        __syncthreads();
    }
    if (tid == 0) {
        float mean = rs[0] / (float)N_NODES;
        float var  = rq[0] / (float)N_NODES - mean * mean;
        float rstd = rsqrtf(var + EPS_BN);
        float sc = gamma[c] * rstd;
        g_scale[c] = sc;
        g_shift[c] = beta[c] - mean * sc;
    }
}

// ---------------- node MLP part 2: h = relu(relu(BN(z)) @ w2 + b2) -----------
__global__ void k_mlp2(const float* __restrict__ w2,
                       const float* __restrict__ b2) {
    __shared__ float sw[HID2 * HID];
    __shared__ float sb[HID];
    __shared__ float ssc[HID2], ssh[HID2];
    int tid = threadIdx.x;
    for (int i = tid; i < HID2 * HID; i += 256) sw[i] = w2[i];
    if (tid < HID) sb[tid] = b2[tid];
    if (tid < HID2) { ssc[tid] = g_scale[tid]; ssh[tid] = g_shift[tid]; }
    __syncthreads();

    int n = blockIdx.x * 8 + (tid >> 5);
    int lane = tid & 31;
    if (n >= N_NODES) return;

    float y0 = fmaxf(fmaf(g_z[n * HID2 + lane],      ssc[lane],      ssh[lane]),      0.f);
    float y1 = fmaxf(fmaf(g_z[n * HID2 + lane + 32], ssc[lane + 32], ssh[lane + 32]), 0.f);
    float acc = sb[lane];
#pragma unroll
    for (int j = 0; j < 32; j++) {
        acc = fmaf(__shfl_sync(FULL, y0, j), sw[j * HID + lane],        acc);
        acc = fmaf(__shfl_sync(FULL, y1, j), sw[(j + 32) * HID + lane], acc);
    }
    g_h[n * HID + lane] = fmaxf(acc, 0.f);   // outer relu from the layer loop
}

// ---------------- output projection: out = h @ w16 + b16 ---------------------
__global__ void k_final(const float* __restrict__ w16,
                        const float* __restrict__ b16,
                        float* __restrict__ out) {
    __shared__ float sw[HID * OUT_CH];
    __shared__ float sb[OUT_CH];
    int tid = threadIdx.x;
    for (int i = tid; i < HID * OUT_CH; i += 256) sw[i] = w16[i];
    if (tid < OUT_CH) sb[tid] = b16[tid];
    __syncthreads();

    int n = blockIdx.x * 8 + (tid >> 5);
    int lane = tid & 31;
    if (n >= N_NODES) return;

    float hv = g_h[n * HID + lane];
    float a0 = sb[lane], a1 = sb[lane + 32];
#pragma unroll
    for (int j = 0; j < 32; j++) {
        float hb = __shfl_sync(FULL, hv, j);
        a0 = fmaf(hb, sw[j * OUT_CH + lane],      a0);
        a1 = fmaf(hb, sw[j * OUT_CH + lane + 32], a1);
    }
    out[n * OUT_CH + lane]      = a0;
    out[n * OUT_CH + lane + 32] = a1;
}

// -----------------------------------------------------------------------------
extern "C" void kernel_launch(void* const* d_in, const int* in_sizes, int n_in,
                              void* d_out, int out_size) {
    const float* x      = (const float*)d_in[0];
    const int*   ei32   = (const int*)d_in[1];     // int32 OR int64 (detected)
    const float* w0     = (const float*)d_in[2];
    const float* b0     = (const float*)d_in[3];
    const float* lin1_w = (const float*)d_in[4];
    const float* lin1_b = (const float*)d_in[5];
    const float* gamma  = (const float*)d_in[6];
    const float* beta   = (const float*)d_in[7];
    const float* lin2_w = (const float*)d_in[8];
    const float* lin2_b = (const float*)d_in[9];
    const float* w16    = (const float*)d_in[10];
    const float* b16    = (const float*)d_in[11];
    float* out = (float*)d_out;

    const int nodeBlocks = (N_NODES + 7) / 8;        // warp per node
    const int edgeBlocks = (N_EDGES + 255) / 256;
    const int nBlocks256 = (N_NODES + 255) / 256;

    // one-time per call: dtype detect + CSR build (multi-block scan)
    k_detect<<<1, 1024>>>(ei32);
    k_zero_deg<<<nBlocks256, 256>>>();
    k_deg<<<edgeBlocks, 256>>>(ei32);
    k_scan1<<<SCAN_GRID, SCAN_BLK>>>();
    k_scan2<<<1, 128>>>();
    k_scan3<<<SCAN_GRID, SCAN_BLK>>>();
    k_fill<<<edgeBlocks, 256>>>(ei32);

    k_input<<<nodeBlocks, 256>>>(x, w0, b0);
    for (int i = 0; i < N_LAYERS; i++) {
        k_fused<<<NBLK_F, 256>>>(lin1_w + i * HID * HID2, lin1_b + i * HID2);
        k_bn<<<HID2, 256>>>(gamma + i * HID2, beta + i * HID2);
        k_mlp2<<<nodeBlocks, 256>>>(lin2_w + i * HID2 * HID, lin2_b + i * HID);
    }
    k_final<<<nodeBlocks, 256>>>(w16, b16, out);
}

// round 13
// speedup vs baseline: 1.0493x; 1.0299x over previous
#include <cuda_runtime.h>

#define N_NODES 100000
#define N_EDGES 1600000
#define IN_CH   128
#define HID     32
#define HID2    64
#define OUT_CH  64
#define N_LAYERS 16

#define EPS_MSG 1e-7f
#define EPS_SM  1e-16f
#define EPS_BN  1e-5f

#define FULL 0xffffffffu
#define NBLK_F 6250       // fused kernel blocks: 16 warps/block, warp per node
#define SCAN_BLK 1024
#define SCAN_GRID ((N_NODES + SCAN_BLK - 1) / SCAN_BLK)   // 98

// ---------------- scratch (static device globals; no allocation) -------------
__device__ float g_h [N_NODES * HID];     // current node features
__device__ float g_z [N_NODES * HID2];    // hidden MLP activations
__device__ int   g_deg[N_NODES];          // in-degree (prep)
__device__ int   g_off[N_NODES + 1];      // CSR offsets by dst
__device__ int   g_cur[N_NODES];          // fill cursors
__device__ int   g_srcs[N_EDGES];         // CSR: src*16 per edge, grouped by dst
__device__ int   g_bsum[SCAN_GRID];       // scan block sums
__device__ float g_psum[NBLK_F * HID2];   // BN partial sums
__device__ float g_psq [NBLK_F * HID2];   // BN partial sum-squares
__device__ float g_scale[HID2];
__device__ float g_shift[HID2];
__device__ int   g_is64;                  // 1 if edge_index is int64

// ---------------- detect edge_index dtype ------------------------------------
// int64 little-endian with values < 2^31 => every odd 32-bit word is 0.
__global__ void k_detect(const int* __restrict__ ei32) {
    __shared__ int any;
    if (threadIdx.x == 0) any = 0;
    __syncthreads();
    int v = ei32[2 * threadIdx.x + 1] | ei32[2 * (threadIdx.x + 1024) + 1];
    if (v != 0) any = 1;
    __syncthreads();
    if (threadIdx.x == 0) g_is64 = (any == 0) ? 1 : 0;
}

// ---------------- one-time CSR build -----------------------------------------
__global__ void k_zero_deg() {
    int i = blockIdx.x * 256 + threadIdx.x;
    if (i < N_NODES) g_deg[i] = 0;
}

__device__ __forceinline__ void raw_edge(const int* __restrict__ ei32,
                                         int e, int& s, int& d) {
    if (g_is64) { s = ei32[2 * e]; d = ei32[2 * (N_EDGES + e)]; }
    else        { s = ei32[e];     d = ei32[N_EDGES + e]; }
    s = min(max(s, 0), N_NODES - 1);
    d = min(max(d, 0), N_NODES - 1);
}

__global__ void k_deg(const int* __restrict__ ei32) {
    int e = blockIdx.x * 256 + threadIdx.x;
    if (e >= N_EDGES) return;
    int s, d; raw_edge(ei32, e, s, d);
    atomicAdd(&g_deg[d], 1);
}

// stage 1: per-block exclusive scan; local excl to g_off, block total to g_bsum
__global__ void k_scan1() {
    __shared__ int tmp[SCAN_BLK];
    int tid = threadIdx.x;
    int i = blockIdx.x * SCAN_BLK + tid;
    int v = (i < N_NODES) ? g_deg[i] : 0;
    tmp[tid] = v;
    __syncthreads();
    for (int o = 1; o < SCAN_BLK; o <<= 1) {
        int t = (tid >= o) ? tmp[tid - o] : 0;
        __syncthreads();
        tmp[tid] += t;
        __syncthreads();
    }
    if (i < N_NODES) g_off[i] = tmp[tid] - v;          // local exclusive
    if (tid == SCAN_BLK - 1) g_bsum[blockIdx.x] = tmp[tid];
}

// stage 2: one small block scans the 98 block sums (exclusive, in place)
__global__ void k_scan2() {
    __shared__ int tmp[128];
    int tid = threadIdx.x;
    int v = (tid < SCAN_GRID) ? g_bsum[tid] : 0;
    tmp[tid] = v;
    __syncthreads();
    for (int o = 1; o < 128; o <<= 1) {
        int t = (tid >= o) ? tmp[tid - o] : 0;
        __syncthreads();
        tmp[tid] += t;
        __syncthreads();
    }
    if (tid < SCAN_GRID) g_bsum[tid] = tmp[tid] - v;
    if (tid == 127) g_off[N_NODES] = tmp[tid];          // total = N_EDGES
}

// stage 3: add block offsets; init cursors
__global__ void k_scan3() {
    int i = blockIdx.x * SCAN_BLK + threadIdx.x;
    if (i >= N_NODES) return;
    int o = g_off[i] + g_bsum[blockIdx.x];
    g_off[i] = o;
    g_cur[i] = o;
}

__global__ void k_fill(const int* __restrict__ ei32) {
    int e = blockIdx.x * 256 + threadIdx.x;
    if (e >= N_EDGES) return;
    int s, d; raw_edge(ei32, e, s, d);
    int p = atomicAdd(&g_cur[d], 1);
    g_srcs[p] = s * 16;      // pre-scaled for float2 indexing
}

// ---------------- input projection: h = x @ w0 + b0 --------------------------
__global__ __launch_bounds__(512) void k_input(const float* __restrict__ x,
                        const float* __restrict__ w0,
                        const float* __restrict__ b0) {
    __shared__ float sw[IN_CH * HID];
    __shared__ float sb[HID];
    int tid = threadIdx.x;
    for (int i = tid; i < IN_CH * HID; i += 512) sw[i] = w0[i];
    if (tid < HID) sb[tid] = b0[tid];
    __syncthreads();

    int n = blockIdx.x * 16 + (tid >> 5);
    int lane = tid & 31;
    if (n >= N_NODES) return;

    const float* xr = x + (long long)n * IN_CH;
    float acc = sb[lane];
#pragma unroll
    for (int k0 = 0; k0 < IN_CH; k0 += 32) {
        float xv = xr[k0 + lane];
#pragma unroll
        for (int j = 0; j < 32; j++) {
            float xb = __shfl_sync(FULL, xv, j);
            acc = fmaf(xb, sw[(k0 + j) * HID + lane], acc);
        }
    }
    g_h[n * HID + lane] = acc;
}

// ---------------- fused edge aggregation + MLP1 + BN partials ----------------
// Warp per dst node (natural order: warps of a block stream contiguous CSR
// ranges — R11 showed locality beats degree-balancing).
// Gather: half-warp per edge, 2 channels per lane (float2), 4 independent
// gathers in flight (R10/R12 showed this beats quarter-warp/float4).
// exp in-register (R9: gathered bytes bind, MUFU is free).
// No max subtraction: m = relu(h)+eps is O(10) (BN renormalizes every layer),
// so exp(m) cannot overflow and num/den is shift-invariant.
// 16 warps/block halves the per-block w1 reload traffic vs 8 warps.
__global__ __launch_bounds__(512) void k_fused(const float* __restrict__ w1,
                        const float* __restrict__ b1) {
    __shared__ float sw[HID * HID2];
    __shared__ float sb[HID2];
    __shared__ float bsum[HID2], bsq[HID2];
    int tid = threadIdx.x;
    for (int i = tid; i < HID * HID2; i += 512) sw[i] = w1[i];
    if (tid < HID2) { sb[tid] = b1[tid]; bsum[tid] = 0.f; bsq[tid] = 0.f; }
    __syncthreads();

    int n = blockIdx.x * 16 + (tid >> 5);   // grid*16 == N_NODES exactly
    int lane = tid & 31;

    int cp   = lane & 15;      // channel pair 0..15
    int half = lane >> 4;      // which edge of the pair
    int beg = g_off[n];
    int end = g_off[n + 1];
    const float2* __restrict__ h2 = (const float2*)g_h;

    float d0 = 0.f, m0s = 0.f, d1 = 0.f, m1s = 0.f;
    int i = beg + half;
    // 4-way unroll: four independent float2 gathers in flight per lane
    for (; i + 6 < end; i += 8) {
        float2 hA = h2[g_srcs[i]     + cp];
        float2 hB = h2[g_srcs[i + 2] + cp];
        float2 hC = h2[g_srcs[i + 4] + cp];
        float2 hD = h2[g_srcs[i + 6] + cp];
        float a0 = fmaxf(hA.x, 0.f) + EPS_MSG, a1 = fmaxf(hA.y, 0.f) + EPS_MSG;
        float b0v = fmaxf(hB.x, 0.f) + EPS_MSG, b1v = fmaxf(hB.y, 0.f) + EPS_MSG;
        float c0 = fmaxf(hC.x, 0.f) + EPS_MSG, c1 = fmaxf(hC.y, 0.f) + EPS_MSG;
        float e0v = fmaxf(hD.x, 0.f) + EPS_MSG, e1v = fmaxf(hD.y, 0.f) + EPS_MSG;
        float xA0 = __expf(a0), xA1 = __expf(a1);
        float xB0 = __expf(b0v), xB1 = __expf(b1v);
        float xC0 = __expf(c0), xC1 = __expf(c1);
        float xD0 = __expf(e0v), xD1 = __expf(e1v);
        d0  += (xA0 + xB0) + (xC0 + xD0);
        m0s += (xA0 * a0 + xB0 * b0v) + (xC0 * c0 + xD0 * e0v);
        d1  += (xA1 + xB1) + (xC1 + xD1);
        m1s += (xA1 * a1 + xB1 * b1v) + (xC1 * c1 + xD1 * e1v);
    }
    for (; i < end; i += 2) {
        float2 hA = h2[g_srcs[i] + cp];
        float a0 = fmaxf(hA.x, 0.f) + EPS_MSG, a1 = fmaxf(hA.y, 0.f) + EPS_MSG;
        float xA0 = __expf(a0), xA1 = __expf(a1);
        d0 += xA0;  m0s += xA0 * a0;
        d1 += xA1;  m1s += xA1 * a1;
    }
    // combine the two half-warps
    d0  += __shfl_xor_sync(FULL, d0, 16);
    m0s += __shfl_xor_sync(FULL, m0s, 16);
    d1  += __shfl_xor_sync(FULL, d1, 16);
    m1s += __shfl_xor_sync(FULL, m1s, 16);

    float2 hv = ((const float2*)g_h)[n * 16 + cp];
    float ov0 = m0s / (d0 + EPS_SM) + hv.x;   // channel 2*cp
    float ov1 = m1s / (d1 + EPS_SM) + hv.y;   // channel 2*cp+1

    // GEMM: z[n, :] = ov @ w1 + b1 ; lane c handles outputs c and c+32
    float a0 = sb[lane], a1 = sb[lane + 32];
#pragma unroll
    for (int q = 0; q < 16; q++) {
        float o0 = __shfl_sync(FULL, ov0, q);
        float o1 = __shfl_sync(FULL, ov1, q);
        a0 = fmaf(o0, sw[(2 * q) * HID2 + lane],          a0);
        a1 = fmaf(o0, sw[(2 * q) * HID2 + lane + 32],     a1);
        a0 = fmaf(o1, sw[(2 * q + 1) * HID2 + lane],      a0);
        a1 = fmaf(o1, sw[(2 * q + 1) * HID2 + lane + 32], a1);
    }
    g_z[n * HID2 + lane]      = a0;
    g_z[n * HID2 + lane + 32] = a1;

    atomicAdd(&bsum[lane],      a0); atomicAdd(&bsq[lane],      a0 * a0);
    atomicAdd(&bsum[lane + 32], a1); atomicAdd(&bsq[lane + 32], a1 * a1);
    __syncthreads();
    if (tid < HID2) {
        g_psum[blockIdx.x * HID2 + tid] = bsum[tid];
        g_psq [blockIdx.x * HID2 + tid] = bsq[tid];
    }
}

// ---------------- BN finalize: reduce partials; fold into scale/shift --------
__global__ void k_bn(const float* __restrict__ gamma,
                     const float* __restrict__ beta) {
    __shared__ float rs[256], rq[256];
    int c = blockIdx.x;
    int tid = threadIdx.x;
    float s = 0.f, q = 0.f;
    for (int b = tid; b < NBLK_F; b += 256) {
        s += g_psum[b * HID2 + c];
        q += g_psq [b * HID2 + c];
    }
    rs[tid] = s; rq[tid] = q;
    __syncthreads();
    for (int o = 128; o > 0; o >>= 1) {
        if (tid < o) { rs[tid] += rs[tid + o]; rq[tid] += rq[tid + o]; }
        __syncthreads();
    }
    if (tid == 0) {
        float mean = rs[0] / (float)N_NODES;
        float var  = rq[0] / (float)N_NODES - mean * mean;
        float rstd = rsqrtf(var + EPS_BN);
        float sc = gamma[c] * rstd;
        g_scale[c] = sc;
        g_shift[c] = beta[c] - mean * sc;
    }
}

// ---------------- node MLP part 2: h = relu(relu(BN(z)) @ w2 + b2) -----------
__global__ __launch_bounds__(512) void k_mlp2(const float* __restrict__ w2,
                       const float* __restrict__ b2) {
    __shared__ float sw[HID2 * HID];
    __shared__ float sb[HID];
    __shared__ float ssc[HID2], ssh[HID2];
    int tid = threadIdx.x;
    for (int i = tid; i < HID2 * HID; i += 512) sw[i] = w2[i];
    if (tid < HID) sb[tid] = b2[tid];
    if (tid < HID2) { ssc[tid] = g_scale[tid]; ssh[tid] = g_shift[tid]; }
    __syncthreads();

    int n = blockIdx.x * 16 + (tid >> 5);
    int lane = tid & 31;
    if (n >= N_NODES) return;

    float y0 = fmaxf(fmaf(g_z[n * HID2 + lane],      ssc[lane],      ssh[lane]),      0.f);
    float y1 = fmaxf(fmaf(g_z[n * HID2 + lane + 32], ssc[lane + 32], ssh[lane + 32]), 0.f);
    float acc = sb[lane];
#pragma unroll
    for (int j = 0; j < 32; j++) {
        acc = fmaf(__shfl_sync(FULL, y0, j), sw[j * HID + lane],        acc);
        acc = fmaf(__shfl_sync(FULL, y1, j), sw[(j + 32) * HID + lane], acc);
    }
    g_h[n * HID + lane] = fmaxf(acc, 0.f);   // outer relu from the layer loop
}

// ---------------- output projection: out = h @ w16 + b16 ---------------------
__global__ __launch_bounds__(512) void k_final(const float* __restrict__ w16,
                        const float* __restrict__ b16,
                        float* __restrict__ out) {
    __shared__ float sw[HID * OUT_CH];
    __shared__ float sb[OUT_CH];
    int tid = threadIdx.x;
    for (int i = tid; i < HID * OUT_CH; i += 512) sw[i] = w16[i];
    if (tid < OUT_CH) sb[tid] = b16[tid];
    __syncthreads();

    int n = blockIdx.x * 16 + (tid >> 5);
    int lane = tid & 31;
    if (n >= N_NODES) return;

    float hv = g_h[n * HID + lane];
    float a0 = sb[lane], a1 = sb[lane + 32];
#pragma unroll
    for (int j = 0; j < 32; j++) {
        float hb = __shfl_sync(FULL, hv, j);
        a0 = fmaf(hb, sw[j * OUT_CH + lane],      a0);
        a1 = fmaf(hb, sw[j * OUT_CH + lane + 32], a1);
    }
    out[n * OUT_CH + lane]      = a0;
    out[n * OUT_CH + lane + 32] = a1;
}

// -----------------------------------------------------------------------------
extern "C" void kernel_launch(void* const* d_in, const int* in_sizes, int n_in,
                              void* d_out, int out_size) {
    const float* x      = (const float*)d_in[0];
    const int*   ei32   = (const int*)d_in[1];     // int32 OR int64 (detected)
    const float* w0     = (const float*)d_in[2];
    const float* b0     = (const float*)d_in[3];
    const float* lin1_w = (const float*)d_in[4];
    const float* lin1_b = (const float*)d_in[5];
    const float* gamma  = (const float*)d_in[6];
    const float* beta   = (const float*)d_in[7];
    const float* lin2_w = (const float*)d_in[8];
    const float* lin2_b = (const float*)d_in[9];
    const float* w16    = (const float*)d_in[10];
    const float* b16    = (const float*)d_in[11];
    float* out = (float*)d_out;

    const int nodeBlocks = (N_NODES + 15) / 16;      // warp per node, 16 w/blk
    const int edgeBlocks = (N_EDGES + 255) / 256;
    const int nBlocks256 = (N_NODES + 255) / 256;

    // one-time per call: dtype detect + CSR build (multi-block scan)
    k_detect<<<1, 1024>>>(ei32);
    k_zero_deg<<<nBlocks256, 256>>>();
    k_deg<<<edgeBlocks, 256>>>(ei32);
    k_scan1<<<SCAN_GRID, SCAN_BLK>>>();
    k_scan2<<<1, 128>>>();
    k_scan3<<<SCAN_GRID, SCAN_BLK>>>();
    k_fill<<<edgeBlocks, 256>>>(ei32);

    k_input<<<nodeBlocks, 512>>>(x, w0, b0);
    for (int i = 0; i < N_LAYERS; i++) {
        k_fused<<<NBLK_F, 512>>>(lin1_w + i * HID * HID2, lin1_b + i * HID2);
        k_bn<<<HID2, 256>>>(gamma + i * HID2, beta + i * HID2);
        k_mlp2<<<nodeBlocks, 512>>>(lin2_w + i * HID2 * HID, lin2_b + i * HID);
    }
    k_final<<<nodeBlocks, 512>>>(w16, b16, out);
}

// round 15
// speedup vs baseline: 1.2050x; 1.1484x over previous
#include <cuda_runtime.h>

#define N_NODES 100000
#define N_EDGES 1600000
#define IN_CH   128
#define HID     32
#define HID2    64
#define OUT_CH  64
#define N_LAYERS 16

#define EPS_MSG 1e-7f
#define EPS_SM  1e-16f
#define EPS_BN  1e-5f

#define FULL 0xffffffffu
#define NBLK_F 6250       // fused kernel blocks: 16 warps/block, warp per node
#define SCAN_BLK 1024
#define SCAN_GRID ((N_NODES + SCAN_BLK - 1) / SCAN_BLK)   // 98

// ---------------- scratch (static device globals; no allocation) -------------
__device__ float g_h [N_NODES * HID];     // current node features
__device__ float g_z [N_NODES * HID2];    // hidden acts, quad layout [n][16]x4
__device__ int   g_deg[N_NODES];          // in-degree (prep)
__device__ int   g_off[N_NODES + 1];      // CSR offsets by dst
__device__ int   g_cur[N_NODES];          // fill cursors
__device__ int   g_srcs[N_EDGES];         // CSR: src*16 per edge, grouped by dst
__device__ int   g_bsum[SCAN_GRID];       // scan block sums
__device__ float g_psum[NBLK_F * HID2];   // BN partial sums
__device__ float g_psq [NBLK_F * HID2];   // BN partial sum-squares
__device__ float g_scale[HID2];
__device__ float g_shift[HID2];
__device__ int   g_is64;                  // 1 if edge_index is int64

// ---------------- detect edge_index dtype ------------------------------------
// int64 little-endian with values < 2^31 => every odd 32-bit word is 0.
__global__ void k_detect(const int* __restrict__ ei32) {
    __shared__ int any;
    if (threadIdx.x == 0) any = 0;
    __syncthreads();
    int v = ei32[2 * threadIdx.x + 1] | ei32[2 * (threadIdx.x + 1024) + 1];
    if (v != 0) any = 1;
    __syncthreads();
    if (threadIdx.x == 0) g_is64 = (any == 0) ? 1 : 0;
}

// ---------------- one-time CSR build -----------------------------------------
__global__ void k_zero_deg() {
    int i = blockIdx.x * 256 + threadIdx.x;
    if (i < N_NODES) g_deg[i] = 0;
}

__device__ __forceinline__ void raw_edge(const int* __restrict__ ei32,
                                         int e, int& s, int& d) {
    if (g_is64) { s = ei32[2 * e]; d = ei32[2 * (N_EDGES + e)]; }
    else        { s = ei32[e];     d = ei32[N_EDGES + e]; }
    s = min(max(s, 0), N_NODES - 1);
    d = min(max(d, 0), N_NODES - 1);
}

__global__ void k_deg(const int* __restrict__ ei32) {
    int e = blockIdx.x * 256 + threadIdx.x;
    if (e >= N_EDGES) return;
    int s, d; raw_edge(ei32, e, s, d);
    atomicAdd(&g_deg[d], 1);
}

__global__ void k_scan1() {
    __shared__ int tmp[SCAN_BLK];
    int tid = threadIdx.x;
    int i = blockIdx.x * SCAN_BLK + tid;
    int v = (i < N_NODES) ? g_deg[i] : 0;
    tmp[tid] = v;
    __syncthreads();
    for (int o = 1; o < SCAN_BLK; o <<= 1) {
        int t = (tid >= o) ? tmp[tid - o] : 0;
        __syncthreads();
        tmp[tid] += t;
        __syncthreads();
    }
    if (i < N_NODES) g_off[i] = tmp[tid] - v;          // local exclusive
    if (tid == SCAN_BLK - 1) g_bsum[blockIdx.x] = tmp[tid];
}

__global__ void k_scan2() {
    __shared__ int tmp[128];
    int tid = threadIdx.x;
    int v = (tid < SCAN_GRID) ? g_bsum[tid] : 0;
    tmp[tid] = v;
    __syncthreads();
    for (int o = 1; o < 128; o <<= 1) {
        int t = (tid >= o) ? tmp[tid - o] : 0;
        __syncthreads();
        tmp[tid] += t;
        __syncthreads();
    }
    if (tid < SCAN_GRID) g_bsum[tid] = tmp[tid] - v;
    if (tid == 127) g_off[N_NODES] = tmp[tid];          // total = N_EDGES
}

__global__ void k_scan3() {
    int i = blockIdx.x * SCAN_BLK + threadIdx.x;
    if (i >= N_NODES) return;
    int o = g_off[i] + g_bsum[blockIdx.x];
    g_off[i] = o;
    g_cur[i] = o;
}

__global__ void k_fill(const int* __restrict__ ei32) {
    int e = blockIdx.x * 256 + threadIdx.x;
    if (e >= N_EDGES) return;
    int s, d; raw_edge(ei32, e, s, d);
    int p = atomicAdd(&g_cur[d], 1);
    g_srcs[p] = s * 16;      // pre-scaled for float2 indexing
}

// ---------------- input projection: h = x @ w0 + b0 --------------------------
__global__ __launch_bounds__(512) void k_input(const float* __restrict__ x,
                        const float* __restrict__ w0,
                        const float* __restrict__ b0) {
    __shared__ float sw[IN_CH * HID];
    __shared__ float sb[HID];
    int tid = threadIdx.x;
    for (int i = tid; i < IN_CH * HID; i += 512) sw[i] = w0[i];
    if (tid < HID) sb[tid] = b0[tid];
    __syncthreads();

    int n = blockIdx.x * 16 + (tid >> 5);
    int lane = tid & 31;
    if (n >= N_NODES) return;

    const float* xr = x + (long long)n * IN_CH;
    float acc = sb[lane];
#pragma unroll
    for (int k0 = 0; k0 < IN_CH; k0 += 32) {
        float xv = xr[k0 + lane];
#pragma unroll
        for (int j = 0; j < 32; j++) {
            float xb = __shfl_sync(FULL, xv, j);
            acc = fmaf(xb, sw[(k0 + j) * HID + lane], acc);
        }
    }
    g_h[n * HID + lane] = acc;
}

// ---------------- fused edge aggregation + MLP1 + BN partials ----------------
// Warp per dst node (natural CSR order). Gather: half-warp per edge, float2,
// 4 in flight (proven optimum R10/R12). exp in-register (R9).
// GEMM restructured: ov staged in shared; lane computes an output QUAD
// (c = lane&15) over its j-half via float4 LDS — ~2x fewer instructions.
__global__ __launch_bounds__(512) void k_fused(const float* __restrict__ w1,
                        const float* __restrict__ b1) {
    __shared__ float sw[HID * HID2];      // w1 [32][64] row-major
    __shared__ float sov[16 * HID];       // per-warp ov
    __shared__ float sb[HID2];
    __shared__ float bsum[HID2], bsq[HID2];
    int tid = threadIdx.x;
    for (int i = tid; i < HID * HID2; i += 512) sw[i] = w1[i];
    if (tid < HID2) { sb[tid] = b1[tid]; bsum[tid] = 0.f; bsq[tid] = 0.f; }
    __syncthreads();

    int wid = tid >> 5;
    int n = blockIdx.x * 16 + wid;        // grid*16 == N_NODES exactly
    int lane = tid & 31;

    int cp   = lane & 15;      // channel pair 0..15
    int half = lane >> 4;      // which edge of the pair
    int beg = g_off[n];
    int end = g_off[n + 1];
    const float2* __restrict__ h2 = (const float2*)g_h;

    float d0 = 0.f, m0s = 0.f, d1 = 0.f, m1s = 0.f;
    int i = beg + half;
    for (; i + 6 < end; i += 8) {
        float2 hA = h2[g_srcs[i]     + cp];
        float2 hB = h2[g_srcs[i + 2] + cp];
        float2 hC = h2[g_srcs[i + 4] + cp];
        float2 hD = h2[g_srcs[i + 6] + cp];
        float a0 = fmaxf(hA.x, 0.f) + EPS_MSG, a1 = fmaxf(hA.y, 0.f) + EPS_MSG;
        float b0v = fmaxf(hB.x, 0.f) + EPS_MSG, b1v = fmaxf(hB.y, 0.f) + EPS_MSG;
        float c0 = fmaxf(hC.x, 0.f) + EPS_MSG, c1 = fmaxf(hC.y, 0.f) + EPS_MSG;
        float e0v = fmaxf(hD.x, 0.f) + EPS_MSG, e1v = fmaxf(hD.y, 0.f) + EPS_MSG;
        float xA0 = __expf(a0), xA1 = __expf(a1);
        float xB0 = __expf(b0v), xB1 = __expf(b1v);
        float xC0 = __expf(c0), xC1 = __expf(c1);
        float xD0 = __expf(e0v), xD1 = __expf(e1v);
        d0  += (xA0 + xB0) + (xC0 + xD0);
        m0s += (xA0 * a0 + xB0 * b0v) + (xC0 * c0 + xD0 * e0v);
        d1  += (xA1 + xB1) + (xC1 + xD1);
        m1s += (xA1 * a1 + xB1 * b1v) + (xC1 * c1 + xD1 * e1v);
    }
    for (; i < end; i += 2) {
        float2 hA = h2[g_srcs[i] + cp];
        float a0 = fmaxf(hA.x, 0.f) + EPS_MSG, a1 = fmaxf(hA.y, 0.f) + EPS_MSG;
        float xA0 = __expf(a0), xA1 = __expf(a1);
        d0 += xA0;  m0s += xA0 * a0;
        d1 += xA1;  m1s += xA1 * a1;
    }
    d0  += __shfl_xor_sync(FULL, d0, 16);
    m0s += __shfl_xor_sync(FULL, m0s, 16);
    d1  += __shfl_xor_sync(FULL, d1, 16);
    m1s += __shfl_xor_sync(FULL, m1s, 16);

    float2 hv = h2[n * 16 + cp];
    float ov0 = m0s / (d0 + EPS_SM) + hv.x;
    float ov1 = m1s / (d1 + EPS_SM) + hv.y;
    if (half == 0)
        ((float2*)sov)[wid * 16 + cp] = make_float2(ov0, ov1);
    __syncwarp();

    // GEMM: lane -> output quad c (channels 4c..4c+3), j-half jh
    int c = lane & 15;
    int jh = lane >> 4;
    const float4* __restrict__ sov4 = (const float4*)(sov + wid * HID);
    const float4* __restrict__ sw4  = (const float4*)sw;   // [j][16 quads]
    const float4* __restrict__ sb4  = (const float4*)sb;
    float4 acc;
    if (jh == 0) acc = sb4[c];
    else         acc = make_float4(0.f, 0.f, 0.f, 0.f);
#pragma unroll
    for (int t = 0; t < 4; t++) {
        float4 o4 = sov4[jh * 4 + t];
        int j = jh * 16 + t * 4;
        float4 w;
        w = sw4[(j + 0) * 16 + c];
        acc.x = fmaf(o4.x, w.x, acc.x); acc.y = fmaf(o4.x, w.y, acc.y);
        acc.z = fmaf(o4.x, w.z, acc.z); acc.w = fmaf(o4.x, w.w, acc.w);
        w = sw4[(j + 1) * 16 + c];
        acc.x = fmaf(o4.y, w.x, acc.x); acc.y = fmaf(o4.y, w.y, acc.y);
        acc.z = fmaf(o4.y, w.z, acc.z); acc.w = fmaf(o4.y, w.w, acc.w);
        w = sw4[(j + 2) * 16 + c];
        acc.x = fmaf(o4.z, w.x, acc.x); acc.y = fmaf(o4.z, w.y, acc.y);
        acc.z = fmaf(o4.z, w.z, acc.z); acc.w = fmaf(o4.z, w.w, acc.w);
        w = sw4[(j + 3) * 16 + c];
        acc.x = fmaf(o4.w, w.x, acc.x); acc.y = fmaf(o4.w, w.y, acc.y);
        acc.z = fmaf(o4.w, w.z, acc.z); acc.w = fmaf(o4.w, w.w, acc.w);
    }
    // combine the two j-halves (lanes l and l+16 share c)
    acc.x += __shfl_xor_sync(FULL, acc.x, 16);
    acc.y += __shfl_xor_sync(FULL, acc.y, 16);
    acc.z += __shfl_xor_sync(FULL, acc.z, 16);
    acc.w += __shfl_xor_sync(FULL, acc.w, 16);
    if (half == 0) {
        ((float4*)g_z)[n * 16 + c] = acc;
        atomicAdd(&bsum[4 * c + 0], acc.x); atomicAdd(&bsq[4 * c + 0], acc.x * acc.x);
        atomicAdd(&bsum[4 * c + 1], acc.y); atomicAdd(&bsq[4 * c + 1], acc.y * acc.y);
        atomicAdd(&bsum[4 * c + 2], acc.z); atomicAdd(&bsq[4 * c + 2], acc.z * acc.z);
        atomicAdd(&bsum[4 * c + 3], acc.w); atomicAdd(&bsq[4 * c + 3], acc.w * acc.w);
    }
    __syncthreads();
    if (tid < HID2) {
        g_psum[blockIdx.x * HID2 + tid] = bsum[tid];
        g_psq [blockIdx.x * HID2 + tid] = bsq[tid];
    }
}

// ---------------- BN finalize: reduce partials; fold into scale/shift --------
__global__ void k_bn(const float* __restrict__ gamma,
                     const float* __restrict__ beta) {
    __shared__ float rs[256], rq[256];
    int c = blockIdx.x;
    int tid = threadIdx.x;
    float s = 0.f, q = 0.f;
    for (int b = tid; b < NBLK_F; b += 256) {
        s += g_psum[b * HID2 + c];
        q += g_psq [b * HID2 + c];
    }
    rs[tid] = s; rq[tid] = q;
    __syncthreads();
    for (int o = 128; o > 0; o >>= 1) {
        if (tid < o) { rs[tid] += rs[tid + o]; rq[tid] += rq[tid + o]; }
        __syncthreads();
    }
    if (tid == 0) {
        float mean = rs[0] / (float)N_NODES;
        float var  = rq[0] / (float)N_NODES - mean * mean;
        float rstd = rsqrtf(var + EPS_BN);
        float sc = gamma[c] * rstd;
        g_scale[c] = sc;
        g_shift[c] = beta[c] - mean * sc;
    }
}

// ---------------- node MLP part 2: h = relu(relu(BN(z)) @ w2 + b2) -----------
// Quad-vectorized GEMM: y staged in shared; lane -> output quad c = lane&7,
// j split 4 ways (jq = lane>>3), shfl_xor(8,16) reduction.
__global__ __launch_bounds__(512) void k_mlp2(const float* __restrict__ w2,
                       const float* __restrict__ b2) {
    __shared__ float sw[HID2 * HID];      // w2 [64][32] row-major
    __shared__ float sy[16 * HID2];       // per-warp y
    __shared__ float sb[HID];
    __shared__ float ssc[HID2], ssh[HID2];
    int tid = threadIdx.x;
    for (int i = tid; i < HID2 * HID; i += 512) sw[i] = w2[i];
    if (tid < HID) sb[tid] = b2[tid];
    if (tid < HID2) { ssc[tid] = g_scale[tid]; ssh[tid] = g_shift[tid]; }
    __syncthreads();

    int wid = tid >> 5;
    int n = blockIdx.x * 16 + wid;        // grid*16 == N_NODES exactly
    int lane = tid & 31;

    if (lane < 16) {
        float4 z4 = ((const float4*)g_z)[n * 16 + lane];
        float4 sc = ((const float4*)ssc)[lane];
        float4 sh = ((const float4*)ssh)[lane];
        float4 y;
        y.x = fmaxf(fmaf(z4.x, sc.x, sh.x), 0.f);
        y.y = fmaxf(fmaf(z4.y, sc.y, sh.y), 0.f);
        y.z = fmaxf(fmaf(z4.z, sc.z, sh.z), 0.f);
        y.w = fmaxf(fmaf(z4.w, sc.w, sh.w), 0.f);
        ((float4*)sy)[wid * 16 + lane] = y;
    }
    __syncwarp();

    int c  = lane & 7;     // output quad (channels 4c..4c+3)
    int jq = lane >> 3;    // j quarter: j in [jq*16, jq*16+16)
    const float4* __restrict__ sy4 = (const float4*)(sy + wid * HID2);
    const float4* __restrict__ sw4 = (const float4*)sw;    // [j][8 quads]
    const float4* __restrict__ sb4 = (const float4*)sb;
    float4 acc;
    if (jq == 0) acc = sb4[c];
    else         acc = make_float4(0.f, 0.f, 0.f, 0.f);
#pragma unroll
    for (int t = 0; t < 4; t++) {
        float4 y4 = sy4[jq * 4 + t];
        int j = jq * 16 + t * 4;
        float4 w;
        w = sw4[(j + 0) * 8 + c];
        acc.x = fmaf(y4.x, w.x, acc.x); acc.y = fmaf(y4.x, w.y, acc.y);
        acc.z = fmaf(y4.x, w.z, acc.z); acc.w = fmaf(y4.x, w.w, acc.w);
        w = sw4[(j + 1) * 8 + c];
        acc.x = fmaf(y4.y, w.x, acc.x); acc.y = fmaf(y4.y, w.y, acc.y);
        acc.z = fmaf(y4.y, w.z, acc.z); acc.w = fmaf(y4.y, w.w, acc.w);
        w = sw4[(j + 2) * 8 + c];
        acc.x = fmaf(y4.z, w.x, acc.x); acc.y = fmaf(y4.z, w.y, acc.y);
        acc.z = fmaf(y4.z, w.z, acc.z); acc.w = fmaf(y4.z, w.w, acc.w);
        w = sw4[(j + 3) * 8 + c];
        acc.x = fmaf(y4.w, w.x, acc.x); acc.y = fmaf(y4.w, w.y, acc.y);
        acc.z = fmaf(y4.w, w.z, acc.z); acc.w = fmaf(y4.w, w.w, acc.w);
    }
    // reduce across the 4 j-quarters
    acc.x += __shfl_xor_sync(FULL, acc.x, 8);
    acc.y += __shfl_xor_sync(FULL, acc.y, 8);
    acc.z += __shfl_xor_sync(FULL, acc.z, 8);
    acc.w += __shfl_xor_sync(FULL, acc.w, 8);
    acc.x += __shfl_xor_sync(FULL, acc.x, 16);
    acc.y += __shfl_xor_sync(FULL, acc.y, 16);
    acc.z += __shfl_xor_sync(FULL, acc.z, 16);
    acc.w += __shfl_xor_sync(FULL, acc.w, 16);
    if (lane < 8) {
        float4 h;
        h.x = fmaxf(acc.x, 0.f);   // outer relu from the layer loop
        h.y = fmaxf(acc.y, 0.f);
        h.z = fmaxf(acc.z, 0.f);
        h.w = fmaxf(acc.w, 0.f);
        ((float4*)g_h)[n * 8 + c] = h;
    }
}

// ---------------- output projection: out = h @ w16 + b16 ---------------------
__global__ __launch_bounds__(512) void k_final(const float* __restrict__ w16,
                        const float* __restrict__ b16,
                        float* __restrict__ out) {
    __shared__ float sw[HID * OUT_CH];
    __shared__ float sb[OUT_CH];
    int tid = threadIdx.x;
    for (int i = tid; i < HID * OUT_CH; i += 512) sw[i] = w16[i];
    if (tid < OUT_CH) sb[tid] = b16[tid];
    __syncthreads();

    int n = blockIdx.x * 16 + (tid >> 5);
    int lane = tid & 31;
    if (n >= N_NODES) return;

    float hv = g_h[n * HID + lane];
    float a0 = sb[lane], a1 = sb[lane + 32];
#pragma unroll
    for (int j = 0; j < 32; j++) {
        float hb = __shfl_sync(FULL, hv, j);
        a0 = fmaf(hb, sw[j * OUT_CH + lane],      a0);
        a1 = fmaf(hb, sw[j * OUT_CH + lane + 32], a1);
    }
    out[n * OUT_CH + lane]      = a0;
    out[n * OUT_CH + lane + 32] = a1;
}

// -----------------------------------------------------------------------------
extern "C" void kernel_launch(void* const* d_in, const int* in_sizes, int n_in,
                              void* d_out, int out_size) {
    const float* x      = (const float*)d_in[0];
    const int*   ei32   = (const int*)d_in[1];     // int32 OR int64 (detected)
    const float* w0     = (const float*)d_in[2];
    const float* b0     = (const float*)d_in[3];
    const float* lin1_w = (const float*)d_in[4];
    const float* lin1_b = (const float*)d_in[5];
    const float* gamma  = (const float*)d_in[6];
    const float* beta   = (const float*)d_in[7];
    const float* lin2_w = (const float*)d_in[8];
    const float* lin2_b = (const float*)d_in[9];
    const float* w16    = (const float*)d_in[10];
    const float* b16    = (const float*)d_in[11];
    float* out = (float*)d_out;

    const int nodeBlocks = (N_NODES + 15) / 16;      // warp per node, 16 w/blk
    const int edgeBlocks = (N_EDGES + 255) / 256;
    const int nBlocks256 = (N_NODES + 255) / 256;

    // one-time per call: dtype detect + CSR build (multi-block scan)
    k_detect<<<1, 1024>>>(ei32);
    k_zero_deg<<<nBlocks256, 256>>>();
    k_deg<<<edgeBlocks, 256>>>(ei32);
    k_scan1<<<SCAN_GRID, SCAN_BLK>>>();
    k_scan2<<<1, 128>>>();
    k_scan3<<<SCAN_GRID, SCAN_BLK>>>();
    k_fill<<<edgeBlocks, 256>>>(ei32);

    k_input<<<nodeBlocks, 512>>>(x, w0, b0);
    for (int i = 0; i < N_LAYERS; i++) {
        k_fused<<<NBLK_F, 512>>>(lin1_w + i * HID * HID2, lin1_b + i * HID2);
        k_bn<<<HID2, 256>>>(gamma + i * HID2, beta + i * HID2);
        k_mlp2<<<nodeBlocks, 512>>>(lin2_w + i * HID2 * HID, lin2_b + i * HID);
    }
    k_final<<<nodeBlocks, 512>>>(w16, b16, out);
}